// round 1
// baseline (speedup 1.0000x reference)
#include <cuda_runtime.h>
#include <math.h>

// ---------------------------------------------------------------------------
// Problem constants (fixed shapes from reference)
// ---------------------------------------------------------------------------
#define BATCH 8
#define SEQ   1024
#define DIM   768
#define HEADS 12
#define HDIM  64
#define ROWS  (BATCH * SEQ)     // 8192
#define QKVN  (3 * DIM)         // 2304
#define ATT_SCALE 0.125f        // 64^-0.5

// ---------------------------------------------------------------------------
// Scratch (device globals: allocation-free per harness rules)
// g_q/g_k/g_v packed as [B, H, N, HDIM] for contiguous attention tiles.
// g_wa is [B*N, DIM] row-major, feeds the projection GEMM.
// ---------------------------------------------------------------------------
__device__ float g_q[BATCH * HEADS * SEQ * HDIM];
__device__ float g_k[BATCH * HEADS * SEQ * HDIM];
__device__ float g_v[BATCH * HEADS * SEQ * HDIM];
__device__ float g_wa[ROWS * DIM];

// ---------------------------------------------------------------------------
// SGEMM: C[M,N] = A[M,K] @ W[K,N] + bias[N]
// 128x128 block tile, BK=8, 256 threads, 8x8 microtile, double-buffered smem.
// SPLIT_QKV: scatter epilogue into g_q/g_k/g_v ([B,H,N,64] packing).
// A_FROM_WA: read A from g_wa device global.
// All dims here are multiples of the tile sizes -> no bounds checks.
// ---------------------------------------------------------------------------
template <bool SPLIT_QKV, bool A_FROM_WA>
__global__ __launch_bounds__(256)
void sgemm_bias(const float* __restrict__ Ain, const float* __restrict__ W,
                const float* __restrict__ bias, float* __restrict__ C,
                int M, int N, int K)
{
    const int BK = 8;
    __shared__ float As[2][BK][128];   // transposed A tile: As[k][row]
    __shared__ float Bs[2][BK][128];   // Bs[k][col]

    const float* A = A_FROM_WA ? g_wa : Ain;

    int tid = threadIdx.x;
    int bm = blockIdx.y * 128;
    int bn = blockIdx.x * 128;

    // global->smem load mapping (one float4 per thread per tile per matrix)
    int a_row = tid >> 1;            // 0..127
    int a_col = (tid & 1) << 2;      // 0 or 4
    int b_row = tid >> 5;            // 0..7
    int b_col = (tid & 31) << 2;     // 0..124

    const float* Aptr = A + (size_t)(bm + a_row) * K + a_col;
    const float* Wptr = W + (size_t)b_row * N + bn + b_col;

    int ty = tid >> 4, tx = tid & 15;
    int cr = ty << 3, cc = tx << 3;

    float acc[8][8];
#pragma unroll
    for (int i = 0; i < 8; ++i)
#pragma unroll
        for (int j = 0; j < 8; ++j) acc[i][j] = 0.0f;

    // preload tile 0
    {
        float4 a4 = *(const float4*)Aptr;
        float4 b4 = *(const float4*)Wptr;
        As[0][a_col + 0][a_row] = a4.x;
        As[0][a_col + 1][a_row] = a4.y;
        As[0][a_col + 2][a_row] = a4.z;
        As[0][a_col + 3][a_row] = a4.w;
        *(float4*)&Bs[0][b_row][b_col] = b4;
    }
    __syncthreads();

    int nk = K >> 3;
    for (int kt = 0; kt < nk; ++kt) {
        int cur = kt & 1;
        float4 na, nb;
        bool has_next = (kt + 1 < nk);
        if (has_next) {
            na = *(const float4*)(Aptr + (kt + 1) * BK);
            nb = *(const float4*)(Wptr + (size_t)(kt + 1) * BK * N);
        }
#pragma unroll
        for (int k = 0; k < BK; ++k) {
            float ar[8], br[8];
            *(float4*)&ar[0] = *(const float4*)&As[cur][k][cr];
            *(float4*)&ar[4] = *(const float4*)&As[cur][k][cr + 4];
            *(float4*)&br[0] = *(const float4*)&Bs[cur][k][cc];
            *(float4*)&br[4] = *(const float4*)&Bs[cur][k][cc + 4];
#pragma unroll
            for (int i = 0; i < 8; ++i)
#pragma unroll
                for (int j = 0; j < 8; ++j)
                    acc[i][j] = fmaf(ar[i], br[j], acc[i][j]);
        }
        if (has_next) {
            int nxt = cur ^ 1;
            As[nxt][a_col + 0][a_row] = na.x;
            As[nxt][a_col + 1][a_row] = na.y;
            As[nxt][a_col + 2][a_row] = na.z;
            As[nxt][a_col + 3][a_row] = na.w;
            *(float4*)&Bs[nxt][b_row][b_col] = nb;
            __syncthreads();
        }
    }

    // epilogue: bias add + store (optionally scattered into q/k/v packing)
#pragma unroll
    for (int i = 0; i < 8; ++i) {
        int row = bm + cr + i;
#pragma unroll
        for (int j4 = 0; j4 < 8; j4 += 4) {
            int col = bn + cc + j4;
            float4 bv = *(const float4*)&bias[col];
            float4 ov;
            ov.x = acc[i][j4 + 0] + bv.x;
            ov.y = acc[i][j4 + 1] + bv.y;
            ov.z = acc[i][j4 + 2] + bv.z;
            ov.w = acc[i][j4 + 3] + bv.w;
            if (SPLIT_QKV) {
                int which = col / DIM;           // 0=q 1=k 2=v
                int rem = col - which * DIM;
                int h = rem >> 6;
                int d = rem & 63;
                int b = row >> 10;
                int n = row & 1023;
                float* dst = (which == 0) ? g_q : (which == 1) ? g_k : g_v;
                *(float4*)&dst[(((b * HEADS + h) * SEQ + n) << 6) + d] = ov;
            } else {
                *(float4*)&C[(size_t)row * N + col] = ov;
            }
        }
    }
}

// ---------------------------------------------------------------------------
// Flash attention (fp32, non-causal). One CTA per (head, 64-row Q tile).
// 256 threads: 16x16 thread grid, 4x4 microtile over the 64x64 S / O tiles.
// Smem: Qt (transposed, [d][r]), KP (Kt then reused as P[r][c]), Vs ([c][d]).
// Exactly 48 KB static shared.
// Online softmax row stats reduced across the 16 lanes sharing a row group
// (ty = tid>>4 constant within each warp half -> shfl_xor 1,2,4,8).
// ---------------------------------------------------------------------------
__global__ __launch_bounds__(256)
void flash_attn()
{
    __shared__ float Qt[64][64];
    __shared__ float KP[64][64];
    __shared__ float Vs[64][64];

    int tid = threadIdx.x;
    int bh = blockIdx.y;                 // 0..95  (b*HEADS + h)
    int q0 = blockIdx.x << 6;            // query tile base

    const float* qb = g_q + (size_t)bh * SEQ * HDIM;
    const float* kb = g_k + (size_t)bh * SEQ * HDIM;
    const float* vb = g_v + (size_t)bh * SEQ * HDIM;

    int lr = tid >> 2;                   // 0..63 : row handled for tile loads
    int lc = (tid & 3) << 4;             // 0,16,32,48

    // load Q tile transposed into smem
#pragma unroll
    for (int i = 0; i < 4; ++i) {
        float4 qv = *(const float4*)(qb + (size_t)(q0 + lr) * HDIM + lc + (i << 2));
        Qt[lc + (i << 2) + 0][lr] = qv.x;
        Qt[lc + (i << 2) + 1][lr] = qv.y;
        Qt[lc + (i << 2) + 2][lr] = qv.z;
        Qt[lc + (i << 2) + 3][lr] = qv.w;
    }

    int ty = tid >> 4, tx = tid & 15;
    int r0 = ty << 2, c0 = tx << 2;

    float m_i[4], l_i[4], o[4][4];
#pragma unroll
    for (int i = 0; i < 4; ++i) {
        m_i[i] = -1e30f;
        l_i[i] = 0.0f;
#pragma unroll
        for (int j = 0; j < 4; ++j) o[i][j] = 0.0f;
    }

#pragma unroll 1
    for (int t = 0; t < SEQ / 64; ++t) {
        __syncthreads();   // prior phase-2 reads of KP/Vs done (covers Q load on t=0)

        // load K tile (transposed) and V tile
#pragma unroll
        for (int i = 0; i < 4; ++i) {
            float4 kv = *(const float4*)(kb + (size_t)((t << 6) + lr) * HDIM + lc + (i << 2));
            KP[lc + (i << 2) + 0][lr] = kv.x;
            KP[lc + (i << 2) + 1][lr] = kv.y;
            KP[lc + (i << 2) + 2][lr] = kv.z;
            KP[lc + (i << 2) + 3][lr] = kv.w;
            float4 vv = *(const float4*)(vb + (size_t)((t << 6) + lr) * HDIM + lc + (i << 2));
            *(float4*)&Vs[lr][lc + (i << 2)] = vv;
        }
        __syncthreads();

        // phase 1: S = Q K^T (4x4 per thread)
        float s[4][4];
#pragma unroll
        for (int i = 0; i < 4; ++i)
#pragma unroll
            for (int j = 0; j < 4; ++j) s[i][j] = 0.0f;

#pragma unroll 8
        for (int k = 0; k < 64; ++k) {
            float a[4], b[4];
            *(float4*)a = *(const float4*)&Qt[k][r0];
            *(float4*)b = *(const float4*)&KP[k][c0];
#pragma unroll
            for (int i = 0; i < 4; ++i)
#pragma unroll
                for (int j = 0; j < 4; ++j)
                    s[i][j] = fmaf(a[i], b[j], s[i][j]);
        }

        // scale + row max (local then across the 16 lanes sharing ty)
        float mt[4];
#pragma unroll
        for (int i = 0; i < 4; ++i) {
            s[i][0] *= ATT_SCALE; s[i][1] *= ATT_SCALE;
            s[i][2] *= ATT_SCALE; s[i][3] *= ATT_SCALE;
            mt[i] = fmaxf(fmaxf(s[i][0], s[i][1]), fmaxf(s[i][2], s[i][3]));
        }
#pragma unroll
        for (int w = 1; w < 16; w <<= 1) {
#pragma unroll
            for (int i = 0; i < 4; ++i)
                mt[i] = fmaxf(mt[i], __shfl_xor_sync(0xffffffffu, mt[i], w));
        }

        // online softmax update
        float p[4][4], corr[4], rs[4];
#pragma unroll
        for (int i = 0; i < 4; ++i) {
            float mn = fmaxf(m_i[i], mt[i]);
            corr[i] = __expf(m_i[i] - mn);   // exp(-inf)=0 on first tile
            m_i[i] = mn;
            rs[i] = 0.0f;
#pragma unroll
            for (int j = 0; j < 4; ++j) {
                p[i][j] = __expf(s[i][j] - mn);
                rs[i] += p[i][j];
            }
        }
#pragma unroll
        for (int w = 1; w < 16; w <<= 1) {
#pragma unroll
            for (int i = 0; i < 4; ++i)
                rs[i] += __shfl_xor_sync(0xffffffffu, rs[i], w);
        }
#pragma unroll
        for (int i = 0; i < 4; ++i) {
            l_i[i] = l_i[i] * corr[i] + rs[i];
#pragma unroll
            for (int j = 0; j < 4; ++j) o[i][j] *= corr[i];
        }

        __syncthreads();   // all threads done reading KP as Kt
        // stash P over the K buffer: P[r][c]
#pragma unroll
        for (int i = 0; i < 4; ++i)
#pragma unroll
            for (int j = 0; j < 4; ++j)
                KP[r0 + i][c0 + j] = p[i][j];
        __syncthreads();

        // phase 2: O += P @ V
#pragma unroll 8
        for (int c = 0; c < 64; ++c) {
            float a[4], b[4];
            a[0] = KP[r0 + 0][c];
            a[1] = KP[r0 + 1][c];
            a[2] = KP[r0 + 2][c];
            a[3] = KP[r0 + 3][c];
            *(float4*)b = *(const float4*)&Vs[c][c0];
#pragma unroll
            for (int i = 0; i < 4; ++i)
#pragma unroll
                for (int j = 0; j < 4; ++j)
                    o[i][j] = fmaf(a[i], b[j], o[i][j]);
        }
    }

    // epilogue: normalize and write into [B, N, DIM] layout for the proj GEMM
    int b_idx = bh / HEADS;
    int h = bh - b_idx * HEADS;
#pragma unroll
    for (int i = 0; i < 4; ++i) {
        float inv = 1.0f / l_i[i];
        int n = q0 + r0 + i;
        float4 ov;
        ov.x = o[i][0] * inv;
        ov.y = o[i][1] * inv;
        ov.z = o[i][2] * inv;
        ov.w = o[i][3] * inv;
        *(float4*)&g_wa[(size_t)(b_idx * SEQ + n) * DIM + (h << 6) + c0] = ov;
    }
}

// ---------------------------------------------------------------------------
// Launch
// ---------------------------------------------------------------------------
extern "C" void kernel_launch(void* const* d_in, const int* in_sizes, int n_in,
                              void* d_out, int out_size)
{
    const float* x      = (const float*)d_in[0];
    const float* w_qkv  = (const float*)d_in[1];
    const float* b_qkv  = (const float*)d_in[2];
    const float* w_proj = (const float*)d_in[3];
    const float* b_proj = (const float*)d_in[4];
    float* out = (float*)d_out;

    // 1) QKV GEMM, scatter into packed q/k/v
    sgemm_bias<true, false><<<dim3(QKVN / 128, ROWS / 128), 256>>>(
        x, w_qkv, b_qkv, nullptr, ROWS, QKVN, DIM);

    // 2) flash attention -> g_wa [B*N, DIM]
    flash_attn<<<dim3(SEQ / 64, BATCH * HEADS), 256>>>();

    // 3) projection GEMM -> out
    sgemm_bias<false, true><<<dim3(DIM / 128, ROWS / 128), 256>>>(
        nullptr, w_proj, b_proj, out, ROWS, DIM, DIM);
}

// round 4
// speedup vs baseline: 1.4687x; 1.4687x over previous
#include <cuda_runtime.h>
#include <cuda_bf16.h>
#include <math.h>
#include <stdint.h>

// ---------------------------------------------------------------------------
// Problem constants
// ---------------------------------------------------------------------------
#define BATCH 8
#define SEQ   1024
#define DIM   768
#define HEADS 12
#define HDIM  64
#define ROWS  (BATCH * SEQ)     // 8192
#define QKVN  (3 * DIM)         // 2304
#define ATT_SCALE 0.125f
#define GK    768               // K dim of both GEMMs

// GEMM tiling
#define BM 128
#define BN 128
#define BK 32
#define NCH (GK / BK)           // 24 chunks
#define GEMM_THREADS 256
#define GS 40                   // smem row stride in bf16 elems (80 B, conflict-free)
#define MATB (BM * GS * 2)      // bytes per matrix tile in smem (10240)
#define STAGEB (4 * MATB)       // Ah, Al, Bh, Bl (40960)
#define SMEM_TOTAL (2 * STAGEB) // 81920

// ---------------------------------------------------------------------------
// Scratch device globals
// ---------------------------------------------------------------------------
__device__ __nv_bfloat16 g_xh[ROWS * DIM], g_xl[ROWS * DIM];
__device__ __nv_bfloat16 g_wqh[QKVN * DIM], g_wql[QKVN * DIM];   // w_qkv^T split
__device__ __nv_bfloat16 g_wph[DIM * DIM], g_wpl[DIM * DIM];     // w_proj^T split
__device__ float g_q[BATCH * HEADS * SEQ * HDIM];
__device__ float g_k[BATCH * HEADS * SEQ * HDIM];
__device__ float g_v[BATCH * HEADS * SEQ * HDIM];
__device__ __nv_bfloat16 g_wah[ROWS * DIM], g_wal[ROWS * DIM];   // attn out split

// ---------------------------------------------------------------------------
// PTX helpers (all plain sm_80-class: cp.async, ldmatrix, mma.sync)
// ---------------------------------------------------------------------------
__device__ __forceinline__ uint32_t smem_u32(const void* p) {
    uint32_t a;
    asm("{ .reg .u64 t; cvta.to.shared.u64 t, %1; cvt.u32.u64 %0, t; }" : "=r"(a) : "l"(p));
    return a;
}
__device__ __forceinline__ void cp16(uint32_t dst, const void* src) {
    asm volatile("cp.async.cg.shared.global [%0], [%1], 16;"
                 :: "r"(dst), "l"(__cvta_generic_to_global(src)) : "memory");
}
#define CP_COMMIT() asm volatile("cp.async.commit_group;" ::: "memory")
#define CP_WAIT(n)  asm volatile("cp.async.wait_group %0;" :: "n"(n) : "memory")

__device__ __forceinline__ void ldsm4(uint32_t addr, uint32_t* r) {
    asm volatile("ldmatrix.sync.aligned.m8n8.x4.shared.b16 {%0,%1,%2,%3}, [%4];"
                 : "=r"(r[0]), "=r"(r[1]), "=r"(r[2]), "=r"(r[3]) : "r"(addr));
}
__device__ __forceinline__ void mma_bf16(float* d, const uint32_t* a, const uint32_t* b) {
    asm volatile(
        "mma.sync.aligned.m16n8k16.row.col.f32.bf16.bf16.f32 "
        "{%0,%1,%2,%3}, {%4,%5,%6,%7}, {%8,%9}, {%0,%1,%2,%3};"
        : "+f"(d[0]), "+f"(d[1]), "+f"(d[2]), "+f"(d[3])
        : "r"(a[0]), "r"(a[1]), "r"(a[2]), "r"(a[3]), "r"(b[0]), "r"(b[1]));
}
__device__ __forceinline__ void bf_split(float v, __nv_bfloat16& h, __nv_bfloat16& l) {
    h = __float2bfloat16(v);
    l = __float2bfloat16(v - __bfloat162float(h));
}

// ---------------------------------------------------------------------------
// Convert kernels
// ---------------------------------------------------------------------------
__global__ void split_x(const float* __restrict__ x) {
    int i = blockIdx.x * blockDim.x + threadIdx.x;
    float4 v = ((const float4*)x)[i];
    __nv_bfloat16 h0, h1, h2, h3, l0, l1, l2, l3;
    bf_split(v.x, h0, l0); bf_split(v.y, h1, l1);
    bf_split(v.z, h2, l2); bf_split(v.w, h3, l3);
    ushort4 H = { __bfloat16_as_ushort(h0), __bfloat16_as_ushort(h1),
                  __bfloat16_as_ushort(h2), __bfloat16_as_ushort(h3) };
    ushort4 L = { __bfloat16_as_ushort(l0), __bfloat16_as_ushort(l1),
                  __bfloat16_as_ushort(l2), __bfloat16_as_ushort(l3) };
    *(ushort4*)&g_xh[4 * i] = H;
    *(ushort4*)&g_xl[4 * i] = L;
}

// w[K=768][N] -> wt hi/lo [N][768]
template <int MODE>   // 0: w_qkv (N=2304), 1: w_proj (N=768)
__global__ void transpose_split(const float* __restrict__ w) {
    const int N = MODE == 0 ? QKVN : DIM;
    __nv_bfloat16* hi = MODE == 0 ? g_wqh : g_wph;
    __nv_bfloat16* lo = MODE == 0 ? g_wql : g_wpl;
    __shared__ float t[32][33];
    int n0 = blockIdx.x * 32, k0 = blockIdx.y * 32;
    int tx = threadIdx.x, ty = threadIdx.y;
#pragma unroll
    for (int j = 0; j < 4; ++j)
        t[ty + 8 * j][tx] = w[(size_t)(k0 + ty + 8 * j) * N + n0 + tx];
    __syncthreads();
#pragma unroll
    for (int j = 0; j < 4; ++j) {
        float v = t[tx][ty + 8 * j];
        __nv_bfloat16 h, l; bf_split(v, h, l);
        size_t o = (size_t)(n0 + ty + 8 * j) * GK + k0 + tx;
        hi[o] = h; lo[o] = l;
    }
}

// ---------------------------------------------------------------------------
// mma.sync bf16-split GEMM: C[M,N] = A(hi+lo)[M,768] @ B(hi+lo)[N,768]^T + bias
// MODE 0: A=x split, B=w_qkv^T split -> scatter into g_q/g_k/g_v (fp32)
// MODE 1: A=wa split, B=w_proj^T split -> Cout
// ---------------------------------------------------------------------------
template <int MODE>
__global__ __launch_bounds__(GEMM_THREADS, 2)
void tc_gemm(const float* __restrict__ bias, float* __restrict__ Cout) {
    extern __shared__ char smem[];
    const __nv_bfloat16* Ah = MODE == 0 ? g_xh : g_wah;
    const __nv_bfloat16* Al = MODE == 0 ? g_xl : g_wal;
    const __nv_bfloat16* Bh = MODE == 0 ? g_wqh : g_wph;
    const __nv_bfloat16* Bl = MODE == 0 ? g_wql : g_wpl;

    int tid = threadIdx.x;
    int bm = blockIdx.y * BM;
    int bn = blockIdx.x * BN;
    uint32_t sb = smem_u32(smem);

    // ---- loader mapping: 2 threads per row, 2x 16B chunks each, 4 matrices
    int lrow = tid >> 1;
    int lch = (tid & 1) * 2;   // chunk base (16B units of 8 bf16)
    const __nv_bfloat16* gsrc[4] = { Ah, Al, Bh, Bl };
    int grow[4] = { bm + lrow, bm + lrow, bn + lrow, bn + lrow };

    auto load_stage = [&](int s, int kc) {
        uint32_t base = sb + s * STAGEB;
#pragma unroll
        for (int m = 0; m < 4; ++m) {
            const __nv_bfloat16* S = gsrc[m] + (size_t)grow[m] * GK + kc * BK + lch * 8;
            uint32_t dst = base + m * MATB + (lrow * GS + lch * 8) * 2;
            cp16(dst, S);
            cp16(dst + 16, S + 8);
        }
    };

    // ---- warp compute mapping
    int wid = tid >> 5, lane = tid & 31;
    int wm = (wid >> 2) * 64;      // 0 or 64
    int wn = (wid & 3) * 32;       // 0/32/64/96
    int mat = lane >> 3, rr = lane & 7;
    int a_r = (mat & 1) * 8 + rr, a_c = (mat >> 1) * 8;   // A frag ldmatrix offsets
    int b_r = (mat >> 1) * 8 + rr, b_c = (mat & 1) * 8;   // B frag ldmatrix offsets

    float acc[4][4][4];
#pragma unroll
    for (int mf = 0; mf < 4; ++mf)
#pragma unroll
        for (int nf = 0; nf < 4; ++nf)
#pragma unroll
            for (int j = 0; j < 4; ++j) acc[mf][nf][j] = 0.0f;

    load_stage(0, 0);
    CP_COMMIT();

#pragma unroll 1
    for (int kc = 0; kc < NCH; ++kc) {
        if (kc + 1 < NCH) { load_stage((kc + 1) & 1, kc + 1); CP_COMMIT(); CP_WAIT(1); }
        else              { CP_WAIT(0); }
        __syncthreads();

        uint32_t st = sb + (kc & 1) * STAGEB;
        uint32_t sAh = st, sAl = st + MATB, sBh = st + 2 * MATB, sBl = st + 3 * MATB;

#pragma unroll
        for (int ks = 0; ks < BK; ks += 16) {
            uint32_t af[4][4], bh[2][4], bl[2][4];
            // B hi/lo fragments (two 16-wide n groups)
#pragma unroll
            for (int ng = 0; ng < 2; ++ng) {
                uint32_t off = ((wn + ng * 16 + b_r) * GS + ks + b_c) * 2;
                ldsm4(sBh + off, bh[ng]);
                ldsm4(sBl + off, bl[ng]);
            }
            // A hi fragments
#pragma unroll
            for (int mf = 0; mf < 4; ++mf)
                ldsm4(sAh + ((wm + mf * 16 + a_r) * GS + ks + a_c) * 2, af[mf]);
            // hi*hi + hi*lo
#pragma unroll
            for (int mf = 0; mf < 4; ++mf)
#pragma unroll
                for (int nf = 0; nf < 4; ++nf) {
                    mma_bf16(acc[mf][nf], af[mf], &bh[nf >> 1][(nf & 1) * 2]);
                    mma_bf16(acc[mf][nf], af[mf], &bl[nf >> 1][(nf & 1) * 2]);
                }
            // A lo fragments (reuse regs) then lo*hi
#pragma unroll
            for (int mf = 0; mf < 4; ++mf)
                ldsm4(sAl + ((wm + mf * 16 + a_r) * GS + ks + a_c) * 2, af[mf]);
#pragma unroll
            for (int mf = 0; mf < 4; ++mf)
#pragma unroll
                for (int nf = 0; nf < 4; ++nf)
                    mma_bf16(acc[mf][nf], af[mf], &bh[nf >> 1][(nf & 1) * 2]);
        }
        __syncthreads();
    }

    // ---- epilogue: bias + store (fp32)
    int g = lane >> 2, tg = lane & 3;
#pragma unroll
    for (int mf = 0; mf < 4; ++mf) {
#pragma unroll
        for (int nf = 0; nf < 4; ++nf) {
            int col = bn + wn + nf * 8 + tg * 2;
            float2 bv = *(const float2*)&bias[col];
#pragma unroll
            for (int half = 0; half < 2; ++half) {
                int row = bm + wm + mf * 16 + g + half * 8;
                float2 ov;
                ov.x = acc[mf][nf][half * 2 + 0] + bv.x;
                ov.y = acc[mf][nf][half * 2 + 1] + bv.y;
                if (MODE == 0) {
                    int which = col / DIM;
                    int rem = col - which * DIM;
                    int h = rem >> 6, d = rem & 63;
                    int b = row >> 10, n = row & 1023;
                    float* dst = (which == 0) ? g_q : (which == 1) ? g_k : g_v;
                    *(float2*)&dst[(((b * HEADS + h) * SEQ + n) << 6) + d] = ov;
                } else {
                    *(float2*)&Cout[(size_t)row * DIM + col] = ov;
                }
            }
        }
    }
}

// ---------------------------------------------------------------------------
// Flash attention (fp32), epilogue emits bf16 hi/lo wa for GEMM2.
// ---------------------------------------------------------------------------
__global__ __launch_bounds__(256)
void flash_attn()
{
    __shared__ float Qt[64][64];
    __shared__ float KP[64][64];
    __shared__ float Vs[64][64];

    int tid = threadIdx.x;
    int bh = blockIdx.y;
    int q0 = blockIdx.x << 6;

    const float* qb = g_q + (size_t)bh * SEQ * HDIM;
    const float* kb = g_k + (size_t)bh * SEQ * HDIM;
    const float* vb = g_v + (size_t)bh * SEQ * HDIM;

    int lr = tid >> 2;
    int lc = (tid & 3) << 4;

#pragma unroll
    for (int i = 0; i < 4; ++i) {
        float4 qv = *(const float4*)(qb + (size_t)(q0 + lr) * HDIM + lc + (i << 2));
        Qt[lc + (i << 2) + 0][lr] = qv.x;
        Qt[lc + (i << 2) + 1][lr] = qv.y;
        Qt[lc + (i << 2) + 2][lr] = qv.z;
        Qt[lc + (i << 2) + 3][lr] = qv.w;
    }

    int ty = tid >> 4, tx = tid & 15;
    int r0 = ty << 2, c0 = tx << 2;

    float m_i[4], l_i[4], o[4][4];
#pragma unroll
    for (int i = 0; i < 4; ++i) {
        m_i[i] = -1e30f;
        l_i[i] = 0.0f;
#pragma unroll
        for (int j = 0; j < 4; ++j) o[i][j] = 0.0f;
    }

#pragma unroll 1
    for (int t = 0; t < SEQ / 64; ++t) {
        __syncthreads();
#pragma unroll
        for (int i = 0; i < 4; ++i) {
            float4 kv = *(const float4*)(kb + (size_t)((t << 6) + lr) * HDIM + lc + (i << 2));
            KP[lc + (i << 2) + 0][lr] = kv.x;
            KP[lc + (i << 2) + 1][lr] = kv.y;
            KP[lc + (i << 2) + 2][lr] = kv.z;
            KP[lc + (i << 2) + 3][lr] = kv.w;
            float4 vv = *(const float4*)(vb + (size_t)((t << 6) + lr) * HDIM + lc + (i << 2));
            *(float4*)&Vs[lr][lc + (i << 2)] = vv;
        }
        __syncthreads();

        float s[4][4];
#pragma unroll
        for (int i = 0; i < 4; ++i)
#pragma unroll
            for (int j = 0; j < 4; ++j) s[i][j] = 0.0f;

#pragma unroll 8
        for (int k = 0; k < 64; ++k) {
            float a[4], b[4];
            *(float4*)a = *(const float4*)&Qt[k][r0];
            *(float4*)b = *(const float4*)&KP[k][c0];
#pragma unroll
            for (int i = 0; i < 4; ++i)
#pragma unroll
                for (int j = 0; j < 4; ++j)
                    s[i][j] = fmaf(a[i], b[j], s[i][j]);
        }

        float mt[4];
#pragma unroll
        for (int i = 0; i < 4; ++i) {
            s[i][0] *= ATT_SCALE; s[i][1] *= ATT_SCALE;
            s[i][2] *= ATT_SCALE; s[i][3] *= ATT_SCALE;
            mt[i] = fmaxf(fmaxf(s[i][0], s[i][1]), fmaxf(s[i][2], s[i][3]));
        }
#pragma unroll
        for (int w = 1; w < 16; w <<= 1)
#pragma unroll
            for (int i = 0; i < 4; ++i)
                mt[i] = fmaxf(mt[i], __shfl_xor_sync(0xffffffffu, mt[i], w));

        float p[4][4], corr[4], rs[4];
#pragma unroll
        for (int i = 0; i < 4; ++i) {
            float mn = fmaxf(m_i[i], mt[i]);
            corr[i] = __expf(m_i[i] - mn);
            m_i[i] = mn;
            rs[i] = 0.0f;
#pragma unroll
            for (int j = 0; j < 4; ++j) {
                p[i][j] = __expf(s[i][j] - mn);
                rs[i] += p[i][j];
            }
        }
#pragma unroll
        for (int w = 1; w < 16; w <<= 1)
#pragma unroll
            for (int i = 0; i < 4; ++i)
                rs[i] += __shfl_xor_sync(0xffffffffu, rs[i], w);
#pragma unroll
        for (int i = 0; i < 4; ++i) {
            l_i[i] = l_i[i] * corr[i] + rs[i];
#pragma unroll
            for (int j = 0; j < 4; ++j) o[i][j] *= corr[i];
        }

        __syncthreads();
#pragma unroll
        for (int i = 0; i < 4; ++i)
#pragma unroll
            for (int j = 0; j < 4; ++j)
                KP[r0 + i][c0 + j] = p[i][j];
        __syncthreads();

#pragma unroll 8
        for (int c = 0; c < 64; ++c) {
            float a[4], b[4];
            a[0] = KP[r0 + 0][c];
            a[1] = KP[r0 + 1][c];
            a[2] = KP[r0 + 2][c];
            a[3] = KP[r0 + 3][c];
            *(float4*)b = *(const float4*)&Vs[c][c0];
#pragma unroll
            for (int i = 0; i < 4; ++i)
#pragma unroll
                for (int j = 0; j < 4; ++j)
                    o[i][j] = fmaf(a[i], b[j], o[i][j]);
        }
    }

    int b_idx = bh / HEADS;
    int h = bh - b_idx * HEADS;
#pragma unroll
    for (int i = 0; i < 4; ++i) {
        float inv = 1.0f / l_i[i];
        int n = q0 + r0 + i;
        size_t base = (size_t)(b_idx * SEQ + n) * DIM + (h << 6) + c0;
        __nv_bfloat16 hh[4], ll[4];
#pragma unroll
        for (int j = 0; j < 4; ++j) bf_split(o[i][j] * inv, hh[j], ll[j]);
        ushort4 H = { __bfloat16_as_ushort(hh[0]), __bfloat16_as_ushort(hh[1]),
                      __bfloat16_as_ushort(hh[2]), __bfloat16_as_ushort(hh[3]) };
        ushort4 L = { __bfloat16_as_ushort(ll[0]), __bfloat16_as_ushort(ll[1]),
                      __bfloat16_as_ushort(ll[2]), __bfloat16_as_ushort(ll[3]) };
        *(ushort4*)&g_wah[base] = H;
        *(ushort4*)&g_wal[base] = L;
    }
}

// ---------------------------------------------------------------------------
// Launch
// ---------------------------------------------------------------------------
extern "C" void kernel_launch(void* const* d_in, const int* in_sizes, int n_in,
                              void* d_out, int out_size)
{
    const float* x      = (const float*)d_in[0];
    const float* w_qkv  = (const float*)d_in[1];
    const float* b_qkv  = (const float*)d_in[2];
    const float* w_proj = (const float*)d_in[3];
    const float* b_proj = (const float*)d_in[4];
    float* out = (float*)d_out;

    cudaFuncSetAttribute(tc_gemm<0>, cudaFuncAttributeMaxDynamicSharedMemorySize, SMEM_TOTAL);
    cudaFuncSetAttribute(tc_gemm<1>, cudaFuncAttributeMaxDynamicSharedMemorySize, SMEM_TOTAL);

    // converts
    split_x<<<(ROWS * DIM / 4) / 256, 256>>>(x);
    transpose_split<0><<<dim3(QKVN / 32, DIM / 32), dim3(32, 8)>>>(w_qkv);
    transpose_split<1><<<dim3(DIM / 32, DIM / 32), dim3(32, 8)>>>(w_proj);

    // QKV GEMM (HMMA) -> packed q/k/v fp32
    tc_gemm<0><<<dim3(QKVN / BN, ROWS / BM), GEMM_THREADS, SMEM_TOTAL>>>(b_qkv, nullptr);

    // flash attention -> wa hi/lo bf16
    flash_attn<<<dim3(SEQ / 64, BATCH * HEADS), 256>>>();

    // projection GEMM (HMMA) -> out
    tc_gemm<1><<<dim3(DIM / BN, ROWS / BM), GEMM_THREADS, SMEM_TOTAL>>>(b_proj, out);
}

// round 6
// speedup vs baseline: 2.6748x; 1.8212x over previous
#include <cuda_runtime.h>
#include <cuda_bf16.h>
#include <math.h>
#include <stdint.h>

// ---------------------------------------------------------------------------
// Problem constants
// ---------------------------------------------------------------------------
#define BATCH 8
#define SEQ   1024
#define DIM   768
#define HEADS 12
#define HDIM  64
#define ROWS  (BATCH * SEQ)     // 8192
#define QKVN  (3 * DIM)         // 2304
#define ATT_SCALE 0.125f
#define GK    768

// GEMM tiling
#define BM 128
#define BN 128
#define BK 32
#define NCH (GK / BK)
#define GEMM_THREADS 256
#define GS 40
#define MATB (BM * GS * 2)
#define STAGEB (4 * MATB)
#define SMEM_TOTAL (2 * STAGEB)

// Flash tiling
#define FS 72                    // smem row stride (bf16): (9r+c)%8 -> conflict-free
#define FTB (64 * FS * 2)        // 9216 B per 64-row tile
#define QTB (128 * FS * 2)       // 18432 B per 128-row Q tile
#define FLASH_SMEM (2 * QTB + 2 * 4 * FTB)   // 110592 B

// ---------------------------------------------------------------------------
// Scratch device globals
// ---------------------------------------------------------------------------
__device__ __nv_bfloat16 g_xh[ROWS * DIM], g_xl[ROWS * DIM];
__device__ __nv_bfloat16 g_wqh[QKVN * DIM], g_wql[QKVN * DIM];
__device__ __nv_bfloat16 g_wph[DIM * DIM], g_wpl[DIM * DIM];
__device__ __nv_bfloat16 g_qh[BATCH * HEADS * SEQ * HDIM], g_ql[BATCH * HEADS * SEQ * HDIM];
__device__ __nv_bfloat16 g_kh[BATCH * HEADS * SEQ * HDIM], g_kl[BATCH * HEADS * SEQ * HDIM];
__device__ __nv_bfloat16 g_vth[BATCH * HEADS * HDIM * SEQ], g_vtl[BATCH * HEADS * HDIM * SEQ]; // V^T
__device__ __nv_bfloat16 g_wah[ROWS * DIM], g_wal[ROWS * DIM];

// ---------------------------------------------------------------------------
// PTX helpers (plain sm_80-class)
// ---------------------------------------------------------------------------
__device__ __forceinline__ uint32_t smem_u32(const void* p) {
    uint32_t a;
    asm("{ .reg .u64 t; cvta.to.shared.u64 t, %1; cvt.u32.u64 %0, t; }" : "=r"(a) : "l"(p));
    return a;
}
__device__ __forceinline__ void cp16(uint32_t dst, const void* src) {
    asm volatile("cp.async.cg.shared.global [%0], [%1], 16;"
                 :: "r"(dst), "l"(__cvta_generic_to_global(src)) : "memory");
}
#define CP_COMMIT() asm volatile("cp.async.commit_group;" ::: "memory")
#define CP_WAIT(n)  asm volatile("cp.async.wait_group %0;" :: "n"(n) : "memory")

__device__ __forceinline__ void ldsm4(uint32_t addr, uint32_t* r) {
    asm volatile("ldmatrix.sync.aligned.m8n8.x4.shared.b16 {%0,%1,%2,%3}, [%4];"
                 : "=r"(r[0]), "=r"(r[1]), "=r"(r[2]), "=r"(r[3]) : "r"(addr));
}
__device__ __forceinline__ void mma_bf16(float* d, const uint32_t* a, const uint32_t* b) {
    asm volatile(
        "mma.sync.aligned.m16n8k16.row.col.f32.bf16.bf16.f32 "
        "{%0,%1,%2,%3}, {%4,%5,%6,%7}, {%8,%9}, {%0,%1,%2,%3};"
        : "+f"(d[0]), "+f"(d[1]), "+f"(d[2]), "+f"(d[3])
        : "r"(a[0]), "r"(a[1]), "r"(a[2]), "r"(a[3]), "r"(b[0]), "r"(b[1]));
}
__device__ __forceinline__ void bf_split(float v, __nv_bfloat16& h, __nv_bfloat16& l) {
    h = __float2bfloat16(v);
    l = __float2bfloat16(v - __bfloat162float(h));
}
__device__ __forceinline__ uint32_t pack2(__nv_bfloat16 a, __nv_bfloat16 b) {
    return (uint32_t)__bfloat16_as_ushort(a) | ((uint32_t)__bfloat16_as_ushort(b) << 16);
}

// ---------------------------------------------------------------------------
// Convert kernels
// ---------------------------------------------------------------------------
__global__ void split_x(const float* __restrict__ x) {
    int i = blockIdx.x * blockDim.x + threadIdx.x;
    float4 v = ((const float4*)x)[i];
    __nv_bfloat16 h0, h1, h2, h3, l0, l1, l2, l3;
    bf_split(v.x, h0, l0); bf_split(v.y, h1, l1);
    bf_split(v.z, h2, l2); bf_split(v.w, h3, l3);
    ushort4 H = { __bfloat16_as_ushort(h0), __bfloat16_as_ushort(h1),
                  __bfloat16_as_ushort(h2), __bfloat16_as_ushort(h3) };
    ushort4 L = { __bfloat16_as_ushort(l0), __bfloat16_as_ushort(l1),
                  __bfloat16_as_ushort(l2), __bfloat16_as_ushort(l3) };
    *(ushort4*)&g_xh[4 * i] = H;
    *(ushort4*)&g_xl[4 * i] = L;
}

template <int MODE>
__global__ void transpose_split(const float* __restrict__ w) {
    const int N = MODE == 0 ? QKVN : DIM;
    __nv_bfloat16* hi = MODE == 0 ? g_wqh : g_wph;
    __nv_bfloat16* lo = MODE == 0 ? g_wql : g_wpl;
    __shared__ float t[32][33];
    int n0 = blockIdx.x * 32, k0 = blockIdx.y * 32;
    int tx = threadIdx.x, ty = threadIdx.y;
#pragma unroll
    for (int j = 0; j < 4; ++j)
        t[ty + 8 * j][tx] = w[(size_t)(k0 + ty + 8 * j) * N + n0 + tx];
    __syncthreads();
#pragma unroll
    for (int j = 0; j < 4; ++j) {
        float v = t[tx][ty + 8 * j];
        __nv_bfloat16 h, l; bf_split(v, h, l);
        size_t o = (size_t)(n0 + ty + 8 * j) * GK + k0 + tx;
        hi[o] = h; lo[o] = l;
    }
}

// ---------------------------------------------------------------------------
// mma.sync bf16-split GEMM
// MODE 0: -> q/k hi/lo [B,H,N,64], v hi/lo transposed [B,H,64,N]
// MODE 1: wa -> Cout (fp32)
// ---------------------------------------------------------------------------
template <int MODE>
__global__ __launch_bounds__(GEMM_THREADS, 2)
void tc_gemm(const float* __restrict__ bias, float* __restrict__ Cout) {
    extern __shared__ char smem[];
    const __nv_bfloat16* Ah = MODE == 0 ? g_xh : g_wah;
    const __nv_bfloat16* Al = MODE == 0 ? g_xl : g_wal;
    const __nv_bfloat16* Bh = MODE == 0 ? g_wqh : g_wph;
    const __nv_bfloat16* Bl = MODE == 0 ? g_wql : g_wpl;

    int tid = threadIdx.x;
    int bm = blockIdx.y * BM;
    int bn = blockIdx.x * BN;
    uint32_t sb = smem_u32(smem);

    int lrow = tid >> 1;
    int lch = (tid & 1) * 2;
    const __nv_bfloat16* gsrc[4] = { Ah, Al, Bh, Bl };
    int grow[4] = { bm + lrow, bm + lrow, bn + lrow, bn + lrow };

    auto load_stage = [&](int s, int kc) {
        uint32_t base = sb + s * STAGEB;
#pragma unroll
        for (int m = 0; m < 4; ++m) {
            const __nv_bfloat16* S = gsrc[m] + (size_t)grow[m] * GK + kc * BK + lch * 8;
            uint32_t dst = base + m * MATB + (lrow * GS + lch * 8) * 2;
            cp16(dst, S);
            cp16(dst + 16, S + 8);
        }
    };

    int wid = tid >> 5, lane = tid & 31;
    int wm = (wid >> 2) * 64;
    int wn = (wid & 3) * 32;
    int mat = lane >> 3, rr = lane & 7;
    int a_r = (mat & 1) * 8 + rr, a_c = (mat >> 1) * 8;
    int b_r = (mat >> 1) * 8 + rr, b_c = (mat & 1) * 8;

    float acc[4][4][4];
#pragma unroll
    for (int mf = 0; mf < 4; ++mf)
#pragma unroll
        for (int nf = 0; nf < 4; ++nf)
#pragma unroll
            for (int j = 0; j < 4; ++j) acc[mf][nf][j] = 0.0f;

    load_stage(0, 0);
    CP_COMMIT();

#pragma unroll 1
    for (int kc = 0; kc < NCH; ++kc) {
        if (kc + 1 < NCH) { load_stage((kc + 1) & 1, kc + 1); CP_COMMIT(); CP_WAIT(1); }
        else              { CP_WAIT(0); }
        __syncthreads();

        uint32_t st = sb + (kc & 1) * STAGEB;
        uint32_t sAh = st, sAl = st + MATB, sBh = st + 2 * MATB, sBl = st + 3 * MATB;

#pragma unroll
        for (int ks = 0; ks < BK; ks += 16) {
            uint32_t af[4][4], bh[2][4], bl[2][4];
#pragma unroll
            for (int ng = 0; ng < 2; ++ng) {
                uint32_t off = ((wn + ng * 16 + b_r) * GS + ks + b_c) * 2;
                ldsm4(sBh + off, bh[ng]);
                ldsm4(sBl + off, bl[ng]);
            }
#pragma unroll
            for (int mf = 0; mf < 4; ++mf)
                ldsm4(sAh + ((wm + mf * 16 + a_r) * GS + ks + a_c) * 2, af[mf]);
#pragma unroll
            for (int mf = 0; mf < 4; ++mf)
#pragma unroll
                for (int nf = 0; nf < 4; ++nf) {
                    mma_bf16(acc[mf][nf], af[mf], &bh[nf >> 1][(nf & 1) * 2]);
                    mma_bf16(acc[mf][nf], af[mf], &bl[nf >> 1][(nf & 1) * 2]);
                }
#pragma unroll
            for (int mf = 0; mf < 4; ++mf)
                ldsm4(sAl + ((wm + mf * 16 + a_r) * GS + ks + a_c) * 2, af[mf]);
#pragma unroll
            for (int mf = 0; mf < 4; ++mf)
#pragma unroll
                for (int nf = 0; nf < 4; ++nf)
                    mma_bf16(acc[mf][nf], af[mf], &bh[nf >> 1][(nf & 1) * 2]);
        }
        __syncthreads();
    }

    int g = lane >> 2, tg = lane & 3;
#pragma unroll
    for (int mf = 0; mf < 4; ++mf) {
#pragma unroll
        for (int nf = 0; nf < 4; ++nf) {
            int col = bn + wn + nf * 8 + tg * 2;
            float2 bv = *(const float2*)&bias[col];
#pragma unroll
            for (int half = 0; half < 2; ++half) {
                int row = bm + wm + mf * 16 + g + half * 8;
                float vx = acc[mf][nf][half * 2 + 0] + bv.x;
                float vy = acc[mf][nf][half * 2 + 1] + bv.y;
                if (MODE == 0) {
                    int which = col / DIM;
                    int rem = col - which * DIM;
                    int h = rem >> 6, d = rem & 63;
                    int b = row >> 10, n = row & 1023;
                    size_t hb = (size_t)(b * HEADS + h);
                    __nv_bfloat16 hx, lx, hy, ly;
                    bf_split(vx, hx, lx); bf_split(vy, hy, ly);
                    if (which == 2) {   // V: store transposed [B,H,64,N]
                        size_t o = (hb * HDIM + d) * SEQ + n;
                        g_vth[o] = hx; g_vtl[o] = lx;
                        g_vth[o + SEQ] = hy; g_vtl[o + SEQ] = ly;
                    } else {
                        size_t o = (hb * SEQ + n) * HDIM + d;
                        __nv_bfloat16* dh = which == 0 ? g_qh : g_kh;
                        __nv_bfloat16* dl = which == 0 ? g_ql : g_kl;
                        *(uint32_t*)&dh[o] = pack2(hx, hy);
                        *(uint32_t*)&dl[o] = pack2(lx, ly);
                    }
                } else {
                    float2 ov = { vx, vy };
                    *(float2*)&Cout[(size_t)row * DIM + col] = ov;
                }
            }
        }
    }
}

// ---------------------------------------------------------------------------
// Flash attention on HMMA, split bf16, 8 warps x 16 q-rows = 128 rows per CTA.
// S = Qh*Kh + Ql*Kh + Qh*Kl ; P split -> O = Ph*Vh + Pl*Vh + Ph*Vl
// ---------------------------------------------------------------------------
__global__ __launch_bounds__(256)
void flash_mma() {
    extern __shared__ char smem[];
    uint32_t sb = smem_u32(smem);
    int tid = threadIdx.x;
    int wid = tid >> 5, lane = tid & 31;
    int bh = blockIdx.y;
    int q0 = blockIdx.x * 128;

    const __nv_bfloat16* qh_src = g_qh + ((size_t)bh * SEQ + q0) * HDIM;
    const __nv_bfloat16* ql_src = g_ql + ((size_t)bh * SEQ + q0) * HDIM;
    const __nv_bfloat16* kh_src = g_kh + (size_t)bh * SEQ * HDIM;
    const __nv_bfloat16* kl_src = g_kl + (size_t)bh * SEQ * HDIM;
    const __nv_bfloat16* vh_src = g_vth + (size_t)bh * HDIM * SEQ;
    const __nv_bfloat16* vl_src = g_vtl + (size_t)bh * HDIM * SEQ;

    // ---- Q tile load (once): 128 rows x 64, hi at 0, lo at QTB
    {
        int qr = tid >> 1, qc = (tid & 1) * 4;
#pragma unroll
        for (int i = 0; i < 4; ++i) {
            uint32_t d = sb + (qr * FS) * 2 + (qc + i) * 16;
            cp16(d, qh_src + (size_t)qr * HDIM + (qc + i) * 8);
            cp16(d + QTB, ql_src + (size_t)qr * HDIM + (qc + i) * 8);
        }
    }

    // ---- stage loader: Kh,Kl,Vh,Vl 64x64 tiles
    int sr = tid >> 2, sc = (tid & 3) * 2;
    auto load_stage = [&](int s, int t) {
        uint32_t base = sb + 2 * QTB + s * 4 * FTB;
        const __nv_bfloat16* kh = kh_src + (size_t)(t * 64 + sr) * HDIM + sc * 8;
        const __nv_bfloat16* kl = kl_src + (size_t)(t * 64 + sr) * HDIM + sc * 8;
        const __nv_bfloat16* vh = vh_src + (size_t)sr * SEQ + t * 64 + sc * 8;
        const __nv_bfloat16* vl = vl_src + (size_t)sr * SEQ + t * 64 + sc * 8;
        uint32_t ro = (sr * FS) * 2 + sc * 16;
#pragma unroll
        for (int i = 0; i < 2; ++i) {
            cp16(base + ro + i * 16, kh + i * 8);
            cp16(base + FTB + ro + i * 16, kl + i * 8);
            cp16(base + 2 * FTB + ro + i * 16, vh + i * 8);
            cp16(base + 3 * FTB + ro + i * 16, vl + i * 8);
        }
    };

    int mat = lane >> 3, rr = lane & 7;
    int a_r = (mat & 1) * 8 + rr, a_c = (mat >> 1) * 8;
    int b_r = (mat >> 1) * 8 + rr, b_c = (mat & 1) * 8;
    int wq = wid * 16;
    int g = lane >> 2, tg = lane & 3;

    float o[8][4];
#pragma unroll
    for (int nf = 0; nf < 8; ++nf)
#pragma unroll
        for (int j = 0; j < 4; ++j) o[nf][j] = 0.0f;
    float m0 = -1e30f, m1 = -1e30f, l0 = 0.0f, l1 = 0.0f;

    load_stage(0, 0);
    CP_COMMIT();

#pragma unroll 1
    for (int t = 0; t < SEQ / 64; ++t) {
        if (t + 1 < SEQ / 64) { load_stage((t + 1) & 1, t + 1); CP_COMMIT(); CP_WAIT(1); }
        else                  { CP_WAIT(0); }
        __syncthreads();

        uint32_t stK = sb + 2 * QTB + (t & 1) * 4 * FTB;
        uint32_t stV = stK + 2 * FTB;

        // ---- S = Q K^T (3 split passes)
        float s[8][4];
#pragma unroll
        for (int nf = 0; nf < 8; ++nf)
#pragma unroll
            for (int j = 0; j < 4; ++j) s[nf][j] = 0.0f;

#pragma unroll
        for (int kf = 0; kf < 4; ++kf) {
            uint32_t qh[4], ql[4];
            uint32_t qoff = ((wq + a_r) * FS + kf * 16 + a_c) * 2;
            ldsm4(sb + qoff, qh);
            ldsm4(sb + QTB + qoff, ql);
#pragma unroll
            for (int ng = 0; ng < 4; ++ng) {
                uint32_t kh[4], kl[4];
                uint32_t off = ((ng * 16 + b_r) * FS + kf * 16 + b_c) * 2;
                ldsm4(stK + off, kh);
                ldsm4(stK + FTB + off, kl);
#pragma unroll
                for (int half = 0; half < 2; ++half) {
                    float* ac = s[ng * 2 + half];
                    mma_bf16(ac, qh, &kh[half * 2]);
                    mma_bf16(ac, ql, &kh[half * 2]);
                    mma_bf16(ac, qh, &kl[half * 2]);
                }
            }
        }

        // ---- softmax (registers): rows g (s[.][0,1]) and g+8 (s[.][2,3])
        float mt0 = -1e30f, mt1 = -1e30f;
#pragma unroll
        for (int nf = 0; nf < 8; ++nf) {
#pragma unroll
            for (int j = 0; j < 4; ++j) s[nf][j] *= ATT_SCALE;
            mt0 = fmaxf(mt0, fmaxf(s[nf][0], s[nf][1]));
            mt1 = fmaxf(mt1, fmaxf(s[nf][2], s[nf][3]));
        }
#pragma unroll
        for (int w = 1; w < 4; w <<= 1) {
            mt0 = fmaxf(mt0, __shfl_xor_sync(0xffffffffu, mt0, w));
            mt1 = fmaxf(mt1, __shfl_xor_sync(0xffffffffu, mt1, w));
        }
        float mn0 = fmaxf(m0, mt0), mn1 = fmaxf(m1, mt1);
        float c0 = __expf(m0 - mn0), c1 = __expf(m1 - mn1);
        m0 = mn0; m1 = mn1;
        float rs0 = 0.0f, rs1 = 0.0f;
#pragma unroll
        for (int nf = 0; nf < 8; ++nf) {
            s[nf][0] = __expf(s[nf][0] - mn0);
            s[nf][1] = __expf(s[nf][1] - mn0);
            s[nf][2] = __expf(s[nf][2] - mn1);
            s[nf][3] = __expf(s[nf][3] - mn1);
            rs0 += s[nf][0] + s[nf][1];
            rs1 += s[nf][2] + s[nf][3];
        }
#pragma unroll
        for (int w = 1; w < 4; w <<= 1) {
            rs0 += __shfl_xor_sync(0xffffffffu, rs0, w);
            rs1 += __shfl_xor_sync(0xffffffffu, rs1, w);
        }
        l0 = l0 * c0 + rs0;
        l1 = l1 * c1 + rs1;
#pragma unroll
        for (int nf = 0; nf < 8; ++nf) {
            o[nf][0] *= c0; o[nf][1] *= c0;
            o[nf][2] *= c1; o[nf][3] *= c1;
        }

        // ---- O += P V (3 split passes); P A-frags packed from registers
#pragma unroll
        for (int kb = 0; kb < 4; ++kb) {
            uint32_t pah[4], pal[4];
#pragma unroll
            for (int q = 0; q < 2; ++q) {       // q=0: nf=2kb (cols +tg*2), q=1: nf=2kb+1 (+8)
                float* sv = s[2 * kb + q];
                __nv_bfloat16 h0, l0b, h1, l1b, h2, l2b, h3, l3b;
                bf_split(sv[0], h0, l0b); bf_split(sv[1], h1, l1b);
                bf_split(sv[2], h2, l2b); bf_split(sv[3], h3, l3b);
                pah[q * 2 + 0] = pack2(h0, h1);  pah[q * 2 + 1] = pack2(h2, h3);
                pal[q * 2 + 0] = pack2(l0b, l1b); pal[q * 2 + 1] = pack2(l2b, l3b);
            }
#pragma unroll
            for (int ng = 0; ng < 4; ++ng) {
                uint32_t vh[4], vl[4];
                uint32_t off = ((ng * 16 + b_r) * FS + kb * 16 + b_c) * 2;
                ldsm4(stV + off, vh);
                ldsm4(stV + FTB + off, vl);
#pragma unroll
                for (int half = 0; half < 2; ++half) {
                    float* ac = o[ng * 2 + half];
                    mma_bf16(ac, pah, &vh[half * 2]);
                    mma_bf16(ac, pal, &vh[half * 2]);
                    mma_bf16(ac, pah, &vl[half * 2]);
                }
            }
        }
        __syncthreads();
    }

    // ---- epilogue: normalize, split, store wa hi/lo [B,N,768]
    float inv0 = 1.0f / l0, inv1 = 1.0f / l1;
    int b_idx = bh / HEADS;
    int h = bh - b_idx * HEADS;
    size_t r0 = (size_t)(b_idx * SEQ + q0 + wq + g) * DIM + h * HDIM;
    size_t r1 = r0 + 8 * DIM;
#pragma unroll
    for (int nf = 0; nf < 8; ++nf) {
        int col = nf * 8 + tg * 2;
        __nv_bfloat16 ha, la, hb, lb;
        bf_split(o[nf][0] * inv0, ha, la); bf_split(o[nf][1] * inv0, hb, lb);
        *(uint32_t*)&g_wah[r0 + col] = pack2(ha, hb);
        *(uint32_t*)&g_wal[r0 + col] = pack2(la, lb);
        bf_split(o[nf][2] * inv1, ha, la); bf_split(o[nf][3] * inv1, hb, lb);
        *(uint32_t*)&g_wah[r1 + col] = pack2(ha, hb);
        *(uint32_t*)&g_wal[r1 + col] = pack2(la, lb);
    }
}

// ---------------------------------------------------------------------------
// Launch
// ---------------------------------------------------------------------------
extern "C" void kernel_launch(void* const* d_in, const int* in_sizes, int n_in,
                              void* d_out, int out_size)
{
    const float* x      = (const float*)d_in[0];
    const float* w_qkv  = (const float*)d_in[1];
    const float* b_qkv  = (const float*)d_in[2];
    const float* w_proj = (const float*)d_in[3];
    const float* b_proj = (const float*)d_in[4];
    float* out = (float*)d_out;

    cudaFuncSetAttribute(tc_gemm<0>, cudaFuncAttributeMaxDynamicSharedMemorySize, SMEM_TOTAL);
    cudaFuncSetAttribute(tc_gemm<1>, cudaFuncAttributeMaxDynamicSharedMemorySize, SMEM_TOTAL);
    cudaFuncSetAttribute(flash_mma, cudaFuncAttributeMaxDynamicSharedMemorySize, FLASH_SMEM);

    split_x<<<(ROWS * DIM / 4) / 256, 256>>>(x);
    transpose_split<0><<<dim3(QKVN / 32, DIM / 32), dim3(32, 8)>>>(w_qkv);
    transpose_split<1><<<dim3(DIM / 32, DIM / 32), dim3(32, 8)>>>(w_proj);

    tc_gemm<0><<<dim3(QKVN / BN, ROWS / BM), GEMM_THREADS, SMEM_TOTAL>>>(b_qkv, nullptr);

    flash_mma<<<dim3(SEQ / 128, BATCH * HEADS), 256, FLASH_SMEM>>>();

    tc_gemm<1><<<dim3(DIM / BN, ROWS / BM), GEMM_THREADS, SMEM_TOTAL>>>(b_proj, out);
}